// round 4
// baseline (speedup 1.0000x reference)
#include <cuda_runtime.h>
#include <math.h>
#include <math_constants.h>

#define Uu    128
#define Nn    512
#define Ff    80
#define FUF   64
#define TOPK  10
#define EPSV  1e-10f
#define C10L2E 14.4269504088896340736f   // 10 * log2(e)
#define L2E    1.44269504088896340736f
#define THRX   127.0f                    // safety cutoff in ex2-arg units

__device__ __forceinline__ float ex2(float x) {
    float r;
    asm("ex2.approx.ftz.f32 %0, %1;" : "=f"(r) : "f"(x));
    return r;
}
__device__ __forceinline__ float warp_sum(float v) {
#pragma unroll
    for (int o = 16; o > 0; o >>= 1) v += __shfl_xor_sync(0xffffffffu, v, o);
    return v;
}

// warp-collective repeated argmax (value desc, index asc) over vals[0..511]
__device__ __forceinline__ void warp_top10_vals(const float* vals, int lane, float* outv) {
    float mv[16];
#pragma unroll
    for (int k = 0; k < 16; k++) mv[k] = vals[(k << 5) + lane];
    for (int t = 0; t < TOPK; t++) {
        float bv = -CUDART_INF_F; int bi = Nn;
#pragma unroll
        for (int k = 0; k < 16; k++) {
            int j = (k << 5) + lane;
            if (mv[k] > bv || (mv[k] == bv && j < bi)) { bv = mv[k]; bi = j; }
        }
#pragma unroll
        for (int o = 16; o > 0; o >>= 1) {
            float ov = __shfl_xor_sync(0xffffffffu, bv, o);
            int   oi = __shfl_xor_sync(0xffffffffu, bi, o);
            if (ov > bv || (ov == bv && oi < bi)) { bv = ov; bi = oi; }
        }
        outv[t] = bv;
        if ((bi & 31) == lane) mv[bi >> 5] = -CUDART_INF_F;
    }
}

__global__ void __launch_bounds__(256, 2) mega_kernel(
    const float* __restrict__ batch, const float* __restrict__ s_div,
    const float* __restrict__ s_ndcg, const float* __restrict__ rel_g,
    float* __restrict__ out)
{
    __shared__ float  ws[8][Nn];          // 16KB: sort/scan buffers, e-scratch, col dump, item partials
    __shared__ float2 sTB[Nn];            // 4KB: (s*C, -A*C) per sorted column
    __shared__ int    sidx[Nn];           // orig index per sorted column
    __shared__ float  sc[Nn], sr[Nn], sinv[Nn], smxx[Nn];
    __shared__ int    slh[Nn];            // lo | hi<<16 per row
    __shared__ float  reg6[2][Nn];        // ndcg: rel_s / relo ; div: rank / mask(int)
    __shared__ float  sarel[TOPK], st10b[TOPK];
    __shared__ float  sscal[8][4];
    __shared__ float  sfin[2 * FUF];

    int bid = blockIdx.x;
    int u = bid >> 1;
    bool isdiv = (bid & 1) != 0;
    int tid = threadIdx.x, w = tid >> 5, lane = tid & 31;
    int t2 = tid + 256;

    // ---------------- setup
    const float* sp = isdiv ? (s_div + (size_t)u * Nn) : (s_ndcg + (size_t)u * Nn);
    float* sv = ws[0];
    sv[tid] = sp[tid]; sv[t2] = sp[t2];
    sidx[tid] = tid;   sidx[t2] = t2;
    sr[tid] = 1.0f;    sr[t2] = 1.0f;
    if (!isdiv) {
        reg6[1][tid] = rel_g[(size_t)u * Nn + tid];
        reg6[1][t2]  = rel_g[(size_t)u * Nn + t2];
    } else {
        ((int*)reg6[1])[tid] = 0; ((int*)reg6[1])[t2] = 0;
    }
    __syncthreads();

    // ---------------- bitonic sort ascending (value, tie: idx asc)
    for (int kk = 2; kk <= Nn; kk <<= 1) {
        for (int jj = kk >> 1; jj > 0; jj >>= 1) {
#pragma unroll
            for (int e = 0; e < 2; e++) {
                int t = tid + (e << 8);
                int ixj = t ^ jj;
                if (ixj > t) {
                    float va = sv[t], vb = sv[ixj];
                    int   ia = sidx[t], ib = sidx[ixj];
                    bool up = ((t & kk) == 0);
                    bool agtb = (va > vb) || (va == vb && ia > ib);
                    if (agtb == up) { sv[t] = vb; sv[ixj] = va; sidx[t] = ib; sidx[ixj] = ia; }
                }
            }
            __syncthreads();
        }
    }

    // ---------------- inclusive prefix scan of sorted values (Hillis-Steele)
    {
        float* a  = ws[1];
        float* b2 = ws[2];
        a[tid] = sv[tid]; a[t2] = sv[t2];
        __syncthreads();
        for (int d = 1; d < Nn; d <<= 1) {
            b2[tid] = a[tid] + ((tid >= d) ? a[tid - d] : 0.f);
            b2[t2]  = a[t2]  + a[t2 - d];
            __syncthreads();
            float* tmp = a; a = b2; b2 = tmp;
        }
        float tot = a[Nn - 1];
        // build TB: T = s*C, B = -A*C, A_j = (2j-N)s_j + tot - 2*pre_j
#pragma unroll
        for (int e = 0; e < 2; e++) {
            int j = tid + (e << 8);
            float ssj = sv[j];
            float pre = a[j] - ssj;
            float A = (float)(2 * j - Nn) * ssj + tot - 2.f * pre;
            sTB[j] = make_float2(ssj * C10L2E, -A * C10L2E);
            if (!isdiv) reg6[0][j] = reg6[1][sidx[j]];   // rel in sorted order
        }
    }
    __syncthreads();

    // ---------------- per-row searches: peak, mxx, [lo,hi)
#pragma unroll
    for (int e = 0; e < 2; e++) {
        int r = tid + (e << 8);
        float v = (float)(Nn - 1 - 2 * r);
#define XF(j) fmaf(v, sTB[j].x, sTB[j].y)
        int pa = 0, pb = Nn - 1;
        while (pa < pb) {
            int m = (pa + pb) >> 1;
            if (XF(m + 1) >= XF(m)) pa = m + 1; else pb = m;
        }
        float mxx = XF(pa);
        if (pa > 0)      mxx = fmaxf(mxx, XF(pa - 1));
        if (pa < Nn - 1) mxx = fmaxf(mxx, XF(pa + 1));
        float thr = mxx - THRX;
        int a0 = 0, b0 = pa;
        while (a0 < b0) { int m = (a0 + b0) >> 1; if (XF(m) >= thr) b0 = m; else a0 = m + 1; }
        int lo = a0;
        a0 = pa; b0 = Nn - 1;
        while (a0 < b0) { int m = (a0 + b0 + 1) >> 1; if (XF(m) >= thr) a0 = m; else b0 = m - 1; }
        int hi = a0 + 1;
        slh[r] = lo | (hi << 16);
        smxx[r] = mxx;
#undef XF
    }
    __syncthreads();

    // ---------------- cache T/B per lane-residue in registers
    float Treg[16], Breg[16];
#pragma unroll
    for (int k = 0; k < 16; k++) {
        float2 tb = sTB[(k << 5) + lane];
        Treg[k] = tb.x; Breg[k] = tb.y;
    }
    float* escr = ws[w];
    float colreg[16];

    // ---------------- sweep 1: softmax row sums + Sinkhorn col pass #1 (r=1)
#pragma unroll
    for (int k = 0; k < 16; k++) colreg[k] = 0.f;
    for (int ii = 0; ii < 64; ii++) {
        int r = w + (ii << 3);
        int lh = slh[r];
        int klo = (lh & 0xffff) >> 5, khi = (((lh >> 16) & 0xffff) + 31) >> 5;
        float v = (float)(Nn - 1 - 2 * r);
        float mxx = smxx[r];
        float sum = 0.f;
#pragma unroll
        for (int k = 0; k < 16; k++) if (k >= klo && k < khi) {
            float x = fmaf(v, Treg[k], Breg[k]);
            float e = ex2(x - mxx);
            escr[(k << 5) + lane] = e;
            sum += e;
        }
        sum = warp_sum(sum);
        float inv = 1.f / sum;
        if (lane == 0) sinv[r] = inv;
#pragma unroll
        for (int k = 0; k < 16; k++) if (k >= klo && k < khi)
            colreg[k] = fmaf(inv, escr[(k << 5) + lane], colreg[k]);
    }
    __syncthreads();
#pragma unroll
    for (int k = 0; k < 16; k++) ws[w][(k << 5) + lane] = colreg[k];
    __syncthreads();
#pragma unroll
    for (int e = 0; e < 2; e++) {
        int j = tid + (e << 8);
        float acc = 0.f;
#pragma unroll
        for (int q = 0; q < 8; q++) acc += ws[q][j];
        sc[j] = (acc == 0.f) ? 0.f : (1.f / fmaxf(acc, EPSV));
    }
    __syncthreads();

    // ---------------- sweeps 2..5: fused row_k + col_{k+1}
    for (int itp = 0; itp < 4; itp++) {
        float creg[16];
#pragma unroll
        for (int k = 0; k < 16; k++) creg[k] = sc[(k << 5) + lane];
#pragma unroll
        for (int k = 0; k < 16; k++) colreg[k] = 0.f;
        for (int ii = 0; ii < 64; ii++) {
            int r = w + (ii << 3);
            int lh = slh[r];
            int klo = (lh & 0xffff) >> 5, khi = (((lh >> 16) & 0xffff) + 31) >> 5;
            float v = (float)(Nn - 1 - 2 * r);
            float mxx = smxx[r], inv = sinv[r];
            float racc = 0.f;
#pragma unroll
            for (int k = 0; k < 16; k++) if (k >= klo && k < khi) {
                float x = fmaf(v, Treg[k], Breg[k]);
                float e = ex2(x - mxx);
                escr[(k << 5) + lane] = e;
                racc = fmaf(creg[k], e, racc);
            }
            racc = warp_sum(racc);
            float rowsum = inv * racc;
            float rold = sr[r];
            float rn = (rowsum == 0.f) ? 0.f : (rold / fmaxf(rold * rowsum, EPSV));
            if (lane == 0) sr[r] = rn;
            float rho = rn * inv;
#pragma unroll
            for (int k = 0; k < 16; k++) if (k >= klo && k < khi)
                colreg[k] = fmaf(rho, escr[(k << 5) + lane], colreg[k]);
        }
        __syncthreads();
#pragma unroll
        for (int k = 0; k < 16; k++) ws[w][(k << 5) + lane] = colreg[k];
        __syncthreads();
#pragma unroll
        for (int e = 0; e < 2; e++) {
            int j = tid + (e << 8);
            float acc = 0.f;
#pragma unroll
            for (int q = 0; q < 8; q++) acc += ws[q][j];
            float c = sc[j];
            sc[j] = (acc == 0.f) ? 0.f : (c / fmaxf(c * acc, EPSV));
        }
        __syncthreads();
    }

    // ---------------- sweep 6
    if (isdiv) {
        float creg[16];
#pragma unroll
        for (int k = 0; k < 16; k++) creg[k] = sc[(k << 5) + lane];
#pragma unroll
        for (int k = 0; k < 16; k++) colreg[k] = 0.f;
        for (int ii = 0; ii < 64; ii++) {
            int r = w + (ii << 3);
            int lh = slh[r];
            int klo = (lh & 0xffff) >> 5, khi = (((lh >> 16) & 0xffff) + 31) >> 5;
            float v = (float)(Nn - 1 - 2 * r);
            float mxx = smxx[r], inv = sinv[r];
            float racc = 0.f;
#pragma unroll
            for (int k = 0; k < 16; k++) if (k >= klo && k < khi) {
                float x = fmaf(v, Treg[k], Breg[k]);
                float e = ex2(x - mxx);
                escr[(k << 5) + lane] = e;
                racc = fmaf(creg[k], e, racc);
            }
            racc = warp_sum(racc);
            float rowsum = inv * racc;
            float rold = sr[r];
            float rn = (rowsum == 0.f) ? 0.f : (rold / fmaxf(rold * rowsum, EPSV));
            float rho = rn * inv * (float)(Nn - r);       // weight w_i = N - i
#pragma unroll
            for (int k = 0; k < 16; k++) if (k >= klo && k < khi)
                colreg[k] = fmaf(rho, escr[(k << 5) + lane], colreg[k]);
        }
        __syncthreads();
#pragma unroll
        for (int k = 0; k < 16; k++) ws[w][(k << 5) + lane] = colreg[k];
        __syncthreads();
#pragma unroll
        for (int e = 0; e < 2; e++) {
            int j = tid + (e << 8);
            float acc = 0.f;
#pragma unroll
            for (int q = 0; q < 8; q++) acc += ws[q][j];
            float arr = sc[j] * acc;                      // approx_rank (sorted col)
            reg6[0][sidx[j]] = 1.f / (1.f + ex2(((float)(Nn - TOPK) - arr) * L2E));
        }
        // top-10 mask from sorted order
        if (tid < TOPK) ((int*)reg6[1])[sidx[Nn - 1 - tid]] = 1;
        __syncthreads();

        // ---- item phase: warp per 64 items, lane owns feats {2l, 2l+1}
        float gx = 0.f, gy = 0.f, hx = 0.f, hy = 0.f;
        float s1 = 0.f, s2 = 0.f, q = 0.f, qh = 0.f;
        for (int ii = 0; ii < 64; ii++) {
            int j = (w << 6) + ii;
            const float2 xy = *(const float2*)(batch + ((size_t)(u * Nn + j)) * Ff + 2 * lane);
            float nr = xy.x * xy.x + xy.y * xy.y;
            nr = warp_sum(nr);
            float nrm = sqrtf(nr);
            float inv = 1.f / fmaxf(nrm, 1e-8f);
            float nn = nr * inv * inv;
            float a = reg6[0][j];
            gx += a * xy.x * inv; gy += a * xy.y * inv;
            int m = ((int*)reg6[1])[j];
            if (m) { hx += xy.x * inv; hy += xy.y * inv; }
            if (lane == 0) {
                s1 += a; s2 += a * a; q += a * a * nn;
                if (m) qh += nn;
            }
        }
        ws[w][2 * lane] = gx;       ws[w][2 * lane + 1] = gy;
        ws[w][FUF + 2 * lane] = hx; ws[w][FUF + 2 * lane + 1] = hy;
        if (lane == 0) {
            sscal[w][0] = s1; sscal[w][1] = s2; sscal[w][2] = q; sscal[w][3] = qh;
        }
        __syncthreads();
        if (tid < FUF) {
            float gf = 0.f, hf = 0.f;
#pragma unroll
            for (int qq = 0; qq < 8; qq++) { gf += ws[qq][tid]; hf += ws[qq][FUF + tid]; }
            sfin[tid] = gf * gf;
            sfin[FUF + tid] = hf * hf;
        }
        __syncthreads();
        if (tid == 0) {
            float G2 = 0.f, H2 = 0.f;
            for (int f = 0; f < FUF; f++) { G2 += sfin[f]; H2 += sfin[FUF + f]; }
            float S1 = 0.f, S2v = 0.f, Q = 0.f, Qh = 0.f;
            for (int qq = 0; qq < 8; qq++) {
                S1 += sscal[qq][0]; S2v += sscal[qq][1];
                Q  += sscal[qq][2]; Qh  += sscal[qq][3];
            }
            float denomA = S1 * S1 - S2v;
            out[2 * Uu + u] = 1.f - (G2 - Q) / denomA;
            out[3 * Uu + u] = (45.f - 0.5f * (H2 - Qh)) / 45.f;
        }
    } else {
        // ndcg: only rows 0..9 matter in final row pass
        for (int rr = w; rr < TOPK; rr += 8) {
            int lh = slh[rr];
            int lo = lh & 0xffff, hi = (lh >> 16) & 0xffff;
            float v = (float)(Nn - 1 - 2 * rr);
            float mxx = smxx[rr], inv = sinv[rr];
            float racc = 0.f, ra = 0.f;
            for (int j = lo + lane; j < hi; j += 32) {
                float2 tb = sTB[j];
                float x = fmaf(v, tb.x, tb.y);
                float e = ex2(x - mxx);
                float ce = sc[j] * e;
                racc += ce;
                ra = fmaf(ce, reg6[0][j], ra);
            }
            racc = warp_sum(racc);
            ra = warp_sum(ra);
            float rowsum = inv * racc;
            float rold = sr[rr];
            float rn = (rowsum == 0.f) ? 0.f : (rold / fmaxf(rold * rowsum, EPSV));
            if (lane == 0) sarel[rr] = rn * inv * ra;
        }
        if (w == 1) warp_top10_vals(reg6[1], lane, st10b);   // top-10 of relevance
        __syncthreads();
        if (tid == 0) {
            float da = 0.f, dm = 0.f, db = 0.f;
            for (int t = 0; t < TOPK; t++) {
                float disc = log2f((float)(t + 2));
                da += (exp2f(sarel[t]) - 1.f) / disc;
                dm += (exp2f(reg6[0][Nn - 1 - t]) - 1.f) / disc;  // rel at top-10 scores
                db += (exp2f(st10b[t]) - 1.f) / disc;
            }
            out[u]      = da / db;
            out[Uu + u] = dm / db;
        }
    }
}

// ---------------------------------------------------------------------------
extern "C" void kernel_launch(void* const* d_in, const int* in_sizes, int n_in,
                              void* d_out, int out_size) {
    const float* batch  = (const float*)d_in[0];
    const float* s_div  = (const float*)d_in[1];
    const float* s_ndcg = (const float*)d_in[2];
    const float* rel    = (const float*)d_in[3];
    float* out = (float*)d_out;

    mega_kernel<<<256, 256>>>(batch, s_div, s_ndcg, rel, out);
}

// round 5
// speedup vs baseline: 1.5402x; 1.5402x over previous
#include <cuda_runtime.h>
#include <math.h>
#include <math_constants.h>

#define Uu    128
#define Nn    512
#define Ff    80
#define FUF   64
#define TOPK  10
#define NCH   16
#define EPSV  1e-10f
#define C10L2E 14.4269504088896340736f   // 10 * log2(e)
#define L2E    1.44269504088896340736f
#define THRX   80.0f                     // cutoff in ex2-arg units

__device__ __forceinline__ float ex2(float x) {
    float r;
    asm("ex2.approx.ftz.f32 %0, %1;" : "=f"(r) : "f"(x));
    return r;
}
__device__ __forceinline__ float warp_sum(float v) {
#pragma unroll
    for (int o = 16; o > 0; o >>= 1) v += __shfl_xor_sync(0xffffffffu, v, o);
    return v;
}

// warp-collective repeated argmax (value desc, index asc) over vals[0..511]
__device__ __forceinline__ void warp_top10_vals(const float* vals, int lane, float* outv) {
    float mv[16];
#pragma unroll
    for (int k = 0; k < 16; k++) mv[k] = vals[(k << 5) + lane];
    for (int t = 0; t < TOPK; t++) {
        float bv = -CUDART_INF_F; int bi = Nn;
#pragma unroll
        for (int k = 0; k < 16; k++) {
            int j = (k << 5) + lane;
            if (mv[k] > bv || (mv[k] == bv && j < bi)) { bv = mv[k]; bi = j; }
        }
#pragma unroll
        for (int o = 16; o > 0; o >>= 1) {
            float ov = __shfl_xor_sync(0xffffffffu, bv, o);
            int   oi = __shfl_xor_sync(0xffffffffu, bi, o);
            if (ov > bv || (ov == bv && oi < bi)) { bv = ov; bi = oi; }
        }
        outv[t] = bv;
        if ((bi & 31) == lane) mv[bi >> 5] = -CUDART_INF_F;
    }
}

__global__ void __launch_bounds__(256, 2) mega_kernel(
    const float* __restrict__ batch, const float* __restrict__ s_div,
    const float* __restrict__ s_ndcg, const float* __restrict__ rel_g,
    float* __restrict__ out)
{
    __shared__ float  sbufA[Nn], sbufB[Nn], sbufC[Nn];
    __shared__ float2 sTB[Nn], srm[Nn];       // (s*C,-A*C) ; (rho, mxx)
    __shared__ int    sidx[Nn], slh[Nn];
    __shared__ float  sc[Nn], sr[Nn], sinv[Nn], smxx[Nn];
    __shared__ float  reg6[2][Nn];            // ndcg: rel_sorted / rel_raw ; div: rank / mask
    __shared__ int    scl[NCH], sch[NCH];
    __shared__ float  sarel[TOPK], st10b[TOPK];
    __shared__ float  sscal[8][4];
    __shared__ float  sfin[2 * FUF];

    int bid = blockIdx.x;
    int u = bid >> 1;
    bool isdiv = (bid & 1) != 0;
    int tid = threadIdx.x, w = tid >> 5, lane = tid & 31;
    int t2 = tid + 256;

    // ---------------- setup
    const float* sp = isdiv ? (s_div + (size_t)u * Nn) : (s_ndcg + (size_t)u * Nn);
    float* sv = sbufA;
    sv[tid] = sp[tid]; sv[t2] = sp[t2];
    sidx[tid] = tid;   sidx[t2] = t2;
    sr[tid] = 1.0f;    sr[t2] = 1.0f;
    if (!isdiv) {
        reg6[1][tid] = rel_g[(size_t)u * Nn + tid];
        reg6[1][t2]  = rel_g[(size_t)u * Nn + t2];
    } else {
        ((int*)reg6[1])[tid] = 0; ((int*)reg6[1])[t2] = 0;
    }
    if (tid < NCH) { scl[tid] = Nn; sch[tid] = -1; }
    __syncthreads();

    // ---------------- bitonic sort ascending (value, tie: idx asc)
    for (int kk = 2; kk <= Nn; kk <<= 1) {
        for (int jj = kk >> 1; jj > 0; jj >>= 1) {
#pragma unroll
            for (int e = 0; e < 2; e++) {
                int t = tid + (e << 8);
                int ixj = t ^ jj;
                if (ixj > t) {
                    float va = sv[t], vb = sv[ixj];
                    int   ia = sidx[t], ib = sidx[ixj];
                    bool up = ((t & kk) == 0);
                    bool agtb = (va > vb) || (va == vb && ia > ib);
                    if (agtb == up) { sv[t] = vb; sv[ixj] = va; sidx[t] = ib; sidx[ixj] = ia; }
                }
            }
            __syncthreads();
        }
    }

    // ---------------- inclusive prefix scan (Hillis-Steele), then build TB
    {
        float* a  = sbufB;
        float* b2 = sbufC;
        a[tid] = sv[tid]; a[t2] = sv[t2];
        __syncthreads();
        for (int d = 1; d < Nn; d <<= 1) {
            b2[tid] = a[tid] + ((tid >= d) ? a[tid - d] : 0.f);
            b2[t2]  = a[t2]  + a[t2 - d];
            __syncthreads();
            float* tmp = a; a = b2; b2 = tmp;
        }
        float tot = a[Nn - 1];
#pragma unroll
        for (int e = 0; e < 2; e++) {
            int j = tid + (e << 8);
            float ssj = sv[j];
            float pre = a[j] - ssj;
            float A = (float)(2 * j - Nn) * ssj + tot - 2.f * pre;
            sTB[j] = make_float2(ssj * C10L2E, -A * C10L2E);
            if (!isdiv) reg6[0][j] = reg6[1][sidx[j]];   // rel in sorted order
        }
    }
    __syncthreads();

    // ---------------- per-row searches: peak (ternary), band [lo,hi), chunk ranges
#pragma unroll
    for (int e = 0; e < 2; e++) {
        int r = tid + (e << 8);
        float v = (float)(Nn - 1 - 2 * r);
#define XF(j) fmaf(v, sTB[j].x, sTB[j].y)
        int pa = 0, pb = Nn - 1;
        while (pa < pb) {
            int m = (pa + pb) >> 1;
            if (XF(m + 1) >= XF(m)) pa = m + 1; else pb = m;
        }
        float mxx = XF(pa);
        if (pa > 0)      mxx = fmaxf(mxx, XF(pa - 1));
        if (pa < Nn - 1) mxx = fmaxf(mxx, XF(pa + 1));
        float thr = mxx - THRX;
        int a0 = 0, b0 = pa;
        while (a0 < b0) { int m = (a0 + b0) >> 1; if (XF(m) >= thr) b0 = m; else a0 = m + 1; }
        int lo = a0;
        a0 = pa; b0 = Nn - 1;
        while (a0 < b0) { int m = (a0 + b0 + 1) >> 1; if (XF(m) >= thr) a0 = m; else b0 = m - 1; }
        int hi = a0 + 1;
#undef XF
        int klo = lo >> 5, khi = (hi + 31) >> 5;
        slh[r] = klo | (khi << 8);
        smxx[r] = mxx;
        for (int ch = klo; ch < khi; ch++) {
            atomicMin(&scl[ch], r);
            atomicMax(&sch[ch], r);
        }
    }
    __syncthreads();

    // ---------------- sweeps
    // sweep 0: col#1 (r=1).  sweeps 1..4: row#k + col#(k+1).
    // sweep 5 (div only): weighted row#5 + approx_rank.  ndcg row#5 handled in tail.
    int nsweep = isdiv ? 6 : 5;
    for (int sweep = 0; sweep < nsweep; sweep++) {
        bool first = (sweep == 0);
        bool last6 = (sweep == 5);
        // ---- pass A: rows (warp-per-row, runtime chunk loop)
        for (int ii = 0; ii < 64; ii++) {
            int r = w + (ii << 3);
            int lh = slh[r];
            int klo = lh & 0xff, khi = (lh >> 8) & 0xff;
            float v = (float)(Nn - 1 - 2 * r);
            float mxx = smxx[r];
            float racc = 0.f;
            const float2* tb = sTB + (klo << 5) + lane;
            const float*  cp = sc  + (klo << 5) + lane;
            if (first) {
                for (int k = klo; k < khi; k++) {
                    float2 t = *tb; tb += 32;
                    racc += ex2(fmaf(v, t.x, t.y) - mxx);
                }
            } else {
                for (int k = klo; k < khi; k++) {
                    float2 t = *tb; tb += 32;
                    float e = ex2(fmaf(v, t.x, t.y) - mxx);
                    racc = fmaf(*cp, e, racc); cp += 32;
                }
            }
            racc = warp_sum(racc);
            float rho;
            if (first) {
                float inv = 1.f / racc;       // racc >= 1 (row max in band)
                if (lane == 0) sinv[r] = inv;
                rho = inv;
            } else {
                float inv = sinv[r];
                float rowsum = inv * racc;
                float rold = sr[r];
                float rn = (rowsum == 0.f) ? 0.f : (rold / fmaxf(rold * rowsum, EPSV));
                if (lane == 0 && !last6) sr[r] = rn;
                rho = rn * inv;
                if (last6) rho *= (float)(Nn - r);
            }
            if (lane == 0) srm[r] = make_float2(rho, mxx);
        }
        __syncthreads();
        // ---- pass B: columns (lane-per-column, loop over chunk's row range)
#pragma unroll
        for (int cc = 0; cc < 2; cc++) {
            int ch = (w << 1) + cc;
            int j = (ch << 5) + lane;
            float2 t = sTB[j];
            int i0 = scl[ch], i1 = sch[ch];
            float cac = 0.f;
            float vf = (float)(Nn - 1 - 2 * i0);
            for (int i = i0; i <= i1; i++) {
                float2 rm = srm[i];
                float e = ex2(fmaf(vf, t.x, t.y) - rm.y);
                cac = fmaf(rm.x, e, cac);
                vf -= 2.0f;
            }
            if (!last6) {
                float c = first ? 1.f : sc[j];
                sc[j] = (cac == 0.f) ? 0.f : (c / fmaxf(c * cac, EPSV));
            } else {
                float arr = sc[j] * cac;      // approx_rank (sorted col)
                reg6[0][sidx[j]] = 1.f / (1.f + ex2(((float)(Nn - TOPK) - arr) * L2E));
            }
        }
        __syncthreads();
    }

    // ---------------- finals
    if (!isdiv) {
        // row#5 for rows 0..9 only, fused with approx_rel
        for (int rr = w; rr < TOPK; rr += 8) {
            int lh = slh[rr];
            int klo = lh & 0xff, khi = (lh >> 8) & 0xff;
            float v = (float)(Nn - 1 - 2 * rr);
            float mxx = smxx[rr], inv = sinv[rr];
            float racc = 0.f, ra = 0.f;
            for (int k = klo; k < khi; k++) {
                int j = (k << 5) + lane;
                float2 t = sTB[j];
                float e = ex2(fmaf(v, t.x, t.y) - mxx);
                float ce = sc[j] * e;
                racc += ce;
                ra = fmaf(ce, reg6[0][j], ra);
            }
            racc = warp_sum(racc);
            ra = warp_sum(ra);
            float rowsum = inv * racc;
            float rold = sr[rr];
            float rn = (rowsum == 0.f) ? 0.f : (rold / fmaxf(rold * rowsum, EPSV));
            if (lane == 0) sarel[rr] = rn * inv * ra;
        }
        if (w == 2) warp_top10_vals(reg6[1], lane, st10b);   // top-10 of relevance
        __syncthreads();
        if (tid == 0) {
            float da = 0.f, dm = 0.f, db = 0.f;
            for (int t = 0; t < TOPK; t++) {
                float disc = log2f((float)(t + 2));
                da += (exp2f(sarel[t]) - 1.f) / disc;
                dm += (exp2f(reg6[0][Nn - 1 - t]) - 1.f) / disc;  // rel at top-10 scores
                db += (exp2f(st10b[t]) - 1.f) / disc;
            }
            out[u]      = da / db;
            out[Uu + u] = dm / db;
        }
    } else {
        // top-10 mask: sorted positions 502..511
        if (tid < TOPK) ((int*)reg6[1])[sidx[Nn - 1 - tid]] = 1;
        __syncthreads();
        // item phase: warp per 64 items, lane owns feats {2l, 2l+1}
        float gx = 0.f, gy = 0.f, hx = 0.f, hy = 0.f;
        float s1 = 0.f, s2 = 0.f, q = 0.f, qh = 0.f;
        for (int ii = 0; ii < 64; ii++) {
            int j = (w << 6) + ii;
            const float2 xy = *(const float2*)(batch + ((size_t)(u * Nn + j)) * Ff + 2 * lane);
            float nr = xy.x * xy.x + xy.y * xy.y;
            nr = warp_sum(nr);
            float nrm = sqrtf(nr);
            float inv = 1.f / fmaxf(nrm, 1e-8f);
            float nn = nr * inv * inv;
            float a = reg6[0][j];
            gx += a * xy.x * inv; gy += a * xy.y * inv;
            int m = ((int*)reg6[1])[j];
            if (m) { hx += xy.x * inv; hy += xy.y * inv; }
            if (lane == 0) {
                s1 += a; s2 += a * a; q += a * a * nn;
                if (m) qh += nn;
            }
        }
        sbufA[(w << 6) + 2 * lane] = gx; sbufA[(w << 6) + 2 * lane + 1] = gy;
        sbufB[(w << 6) + 2 * lane] = hx; sbufB[(w << 6) + 2 * lane + 1] = hy;
        if (lane == 0) {
            sscal[w][0] = s1; sscal[w][1] = s2; sscal[w][2] = q; sscal[w][3] = qh;
        }
        __syncthreads();
        if (tid < FUF) {
            float gf = 0.f, hf = 0.f;
#pragma unroll
            for (int qq = 0; qq < 8; qq++) { gf += sbufA[(qq << 6) + tid]; hf += sbufB[(qq << 6) + tid]; }
            sfin[tid] = gf * gf;
            sfin[FUF + tid] = hf * hf;
        }
        __syncthreads();
        if (tid == 0) {
            float G2 = 0.f, H2 = 0.f;
            for (int f = 0; f < FUF; f++) { G2 += sfin[f]; H2 += sfin[FUF + f]; }
            float S1 = 0.f, S2v = 0.f, Q = 0.f, Qh = 0.f;
            for (int qq = 0; qq < 8; qq++) {
                S1 += sscal[qq][0]; S2v += sscal[qq][1];
                Q  += sscal[qq][2]; Qh  += sscal[qq][3];
            }
            float denomA = S1 * S1 - S2v;
            out[2 * Uu + u] = 1.f - (G2 - Q) / denomA;
            out[3 * Uu + u] = (45.f - 0.5f * (H2 - Qh)) / 45.f;
        }
    }
}

// ---------------------------------------------------------------------------
extern "C" void kernel_launch(void* const* d_in, const int* in_sizes, int n_in,
                              void* d_out, int out_size) {
    const float* batch  = (const float*)d_in[0];
    const float* s_div  = (const float*)d_in[1];
    const float* s_ndcg = (const float*)d_in[2];
    const float* rel    = (const float*)d_in[3];
    float* out = (float*)d_out;

    mega_kernel<<<256, 256>>>(batch, s_div, s_ndcg, rel, out);
}

// round 6
// speedup vs baseline: 3.7044x; 2.4052x over previous
#include <cuda_runtime.h>
#include <math.h>
#include <math_constants.h>

#define Uu    128
#define Nn    512
#define Ff    80
#define FUF   64
#define TOPK  10
#define NCH   16
#define EPSV  1e-10f
#define C10L2E 14.4269504088896340736f   // 10 * log2(e)
#define L2E    1.44269504088896340736f
#define THRX   80.0f                     // cutoff in ex2-arg units

__device__ __forceinline__ float ex2(float x) {
    float r;
    asm("ex2.approx.ftz.f32 %0, %1;" : "=f"(r) : "f"(x));
    return r;
}
__device__ __forceinline__ float warp_sum(float v) {
#pragma unroll
    for (int o = 16; o > 0; o >>= 1) v += __shfl_xor_sync(0xffffffffu, v, o);
    return v;
}

// warp-collective repeated argmax (value desc, index asc) over vals[0..511]
__device__ __forceinline__ void warp_top10_vals(const float* vals, int lane, float* outv) {
    float mv[16];
#pragma unroll
    for (int k = 0; k < 16; k++) mv[k] = vals[(k << 5) + lane];
    for (int t = 0; t < TOPK; t++) {
        float bv = -CUDART_INF_F; int bi = Nn;
#pragma unroll
        for (int k = 0; k < 16; k++) {
            int j = (k << 5) + lane;
            if (mv[k] > bv || (mv[k] == bv && j < bi)) { bv = mv[k]; bi = j; }
        }
#pragma unroll
        for (int o = 16; o > 0; o >>= 1) {
            float ov = __shfl_xor_sync(0xffffffffu, bv, o);
            int   oi = __shfl_xor_sync(0xffffffffu, bi, o);
            if (ov > bv || (ov == bv && oi < bi)) { bv = ov; bi = oi; }
        }
        outv[t] = bv;
        if ((bi & 31) == lane) mv[bi >> 5] = -CUDART_INF_F;
    }
}

__global__ void __launch_bounds__(256, 2) mega_kernel(
    const float* __restrict__ batch, const float* __restrict__ s_div,
    const float* __restrict__ s_ndcg, const float* __restrict__ rel_g,
    float* __restrict__ out)
{
    __shared__ float  sbufA[Nn], sbufB[Nn], sbufC[Nn];
    __shared__ float2 sTB[Nn];                 // (s*C, -A*C) per sorted column
    __shared__ float2 srm[Nn];                 // (rho, mxx) per row
    __shared__ int    sidx[Nn], slh[Nn];
    __shared__ float  smxx[Nn], sinv[Nn], sr[Nn], sc[Nn];
    __shared__ float  reg6[2][Nn];             // ndcg: rel_sorted / rel_raw ; div: rank / mask
    __shared__ int    scl[NCH], sch[NCH];
    __shared__ float  sarel[TOPK], st10b[TOPK];
    __shared__ float  sscal[8][4];
    __shared__ float  sfin[2 * FUF];

    int bid = blockIdx.x;
    int u = bid >> 1;
    bool isdiv = (bid & 1) != 0;
    int tid = threadIdx.x, w = tid >> 5, lane = tid & 31;
    int t2 = tid + 256;

    // ---------------- setup
    const float* sp = isdiv ? (s_div + (size_t)u * Nn) : (s_ndcg + (size_t)u * Nn);
    float* sv = sbufA;
    sv[tid] = sp[tid]; sv[t2] = sp[t2];
    sidx[tid] = tid;   sidx[t2] = t2;
    sr[tid] = 1.0f;    sr[t2] = 1.0f;
    if (!isdiv) {
        reg6[1][tid] = rel_g[(size_t)u * Nn + tid];
        reg6[1][t2]  = rel_g[(size_t)u * Nn + t2];
    } else {
        ((int*)reg6[1])[tid] = 0; ((int*)reg6[1])[t2] = 0;
    }
    if (tid < NCH) { scl[tid] = Nn; sch[tid] = -1; }
    __syncthreads();

    // ---------------- bitonic sort ascending (value, tie: idx asc)
    for (int kk = 2; kk <= Nn; kk <<= 1) {
        for (int jj = kk >> 1; jj > 0; jj >>= 1) {
#pragma unroll
            for (int e = 0; e < 2; e++) {
                int t = tid + (e << 8);
                int ixj = t ^ jj;
                if (ixj > t) {
                    float va = sv[t], vb = sv[ixj];
                    int   ia = sidx[t], ib = sidx[ixj];
                    bool up = ((t & kk) == 0);
                    bool agtb = (va > vb) || (va == vb && ia > ib);
                    if (agtb == up) { sv[t] = vb; sv[ixj] = va; sidx[t] = ib; sidx[ixj] = ia; }
                }
            }
            __syncthreads();
        }
    }

    // ---------------- inclusive prefix scan (Hillis-Steele), then build TB
    {
        float* a  = sbufB;
        float* b2 = sbufC;
        a[tid] = sv[tid]; a[t2] = sv[t2];
        __syncthreads();
        for (int d = 1; d < Nn; d <<= 1) {
            b2[tid] = a[tid] + ((tid >= d) ? a[tid - d] : 0.f);
            b2[t2]  = a[t2]  + a[t2 - d];
            __syncthreads();
            float* tmp = a; a = b2; b2 = tmp;
        }
        float tot = a[Nn - 1];
#pragma unroll
        for (int e = 0; e < 2; e++) {
            int j = tid + (e << 8);
            float ssj = sv[j];
            float pre = a[j] - ssj;
            float A = (float)(2 * j - Nn) * ssj + tot - 2.f * pre;
            sTB[j] = make_float2(ssj * C10L2E, -A * C10L2E);
            if (!isdiv) reg6[0][j] = reg6[1][sidx[j]];   // rel in sorted order
        }
    }
    __syncthreads();

    // ---------------- per-row band: analytic peak j* = N-1-r, two binary searches
#pragma unroll
    for (int e = 0; e < 2; e++) {
        int r = tid + (e << 8);
        float v = (float)(Nn - 1 - 2 * r);
        int jstar = Nn - 1 - r;
        float2 tp = sTB[jstar];
        float mxx = fmaf(v, tp.x, tp.y);       // exact row max (x unimodal, peak at jstar)
        float thr = mxx - THRX;
        int a0 = 0, b0 = jstar;                // x nondecreasing on [0, jstar]
        while (a0 < b0) {
            int m = (a0 + b0) >> 1;
            float2 t = sTB[m];
            if (fmaf(v, t.x, t.y) >= thr) b0 = m; else a0 = m + 1;
        }
        int lo = a0;
        a0 = jstar; b0 = Nn - 1;               // x nonincreasing on [jstar, N-1]
        while (a0 < b0) {
            int m = (a0 + b0 + 1) >> 1;
            float2 t = sTB[m];
            if (fmaf(v, t.x, t.y) >= thr) a0 = m; else b0 = m - 1;
        }
        int hi = a0 + 1;
        slh[r] = lo | (hi << 16);
        smxx[r] = mxx;
        for (int ch = (lo >> 5); ch < ((hi + 31) >> 5); ch++) {
            atomicMin(&scl[ch], r);
            atomicMax(&sch[ch], r);
        }
    }
    __syncthreads();

    // ---------------- sweeps
    // sweep 0: col#1 (r=1).  sweeps 1..4: row#k + col#(k+1).
    // sweep 5 (div only): weighted row#5 + approx_rank.  ndcg row#5 in tail.
    int nsweep = isdiv ? 6 : 5;
    for (int sweep = 0; sweep < nsweep; sweep++) {
        bool first = (sweep == 0);
        bool last6 = (sweep == 5);
        // ---- pass A: thread-per-row, scalar accumulation (no shuffles)
#pragma unroll
        for (int e = 0; e < 2; e++) {
            int r = tid + (e << 8);
            int lh = slh[r];
            int lo = lh & 0xffff, hi = lh >> 16;
            float v = (float)(Nn - 1 - 2 * r);
            float mxx = smxx[r];
            float acc0 = 0.f, acc1 = 0.f;
            int j = lo;
            if (first) {
                for (; j + 2 <= hi; j += 2) {
                    float2 t0 = sTB[j], t1 = sTB[j + 1];
                    acc0 += ex2(fmaf(v, t0.x, t0.y) - mxx);
                    acc1 += ex2(fmaf(v, t1.x, t1.y) - mxx);
                }
                if (j < hi) { float2 t0 = sTB[j]; acc0 += ex2(fmaf(v, t0.x, t0.y) - mxx); }
            } else {
                for (; j + 2 <= hi; j += 2) {
                    float2 t0 = sTB[j], t1 = sTB[j + 1];
                    acc0 = fmaf(sc[j],     ex2(fmaf(v, t0.x, t0.y) - mxx), acc0);
                    acc1 = fmaf(sc[j + 1], ex2(fmaf(v, t1.x, t1.y) - mxx), acc1);
                }
                if (j < hi) { float2 t0 = sTB[j]; acc0 = fmaf(sc[j], ex2(fmaf(v, t0.x, t0.y) - mxx), acc0); }
            }
            float racc = acc0 + acc1;
            float rho;
            if (first) {
                float inv = 1.f / racc;        // racc >= 1 (exp at jstar == 1)
                sinv[r] = inv;
                rho = inv;
            } else {
                float inv = sinv[r];
                float rowsum = inv * racc;
                float rold = sr[r];
                float rn = (rowsum == 0.f) ? 0.f : (rold / fmaxf(rold * rowsum, EPSV));
                if (!last6) sr[r] = rn;
                rho = rn * inv;
                if (last6) rho *= (float)(Nn - r);   // w_i = N - i
            }
            srm[r] = make_float2(rho, mxx);
        }
        __syncthreads();
        // ---- pass B: thread-per-column; warp == one chunk, srm reads broadcast
#pragma unroll
        for (int e = 0; e < 2; e++) {
            int j = tid + (e << 8);
            int ch = j >> 5;                   // warp-uniform
            float2 t = sTB[j];
            int i0 = scl[ch], i1 = sch[ch];
            float a0 = 0.f, a1 = 0.f;
            float vf = (float)(Nn - 1 - 2 * i0);
            int i = i0;
            for (; i + 1 <= i1; i += 2) {
                float2 r0 = srm[i], r1 = srm[i + 1];
                a0 = fmaf(r0.x, ex2(fmaf(vf,       t.x, t.y) - r0.y), a0);
                a1 = fmaf(r1.x, ex2(fmaf(vf - 2.f, t.x, t.y) - r1.y), a1);
                vf -= 4.f;
            }
            if (i <= i1) {
                float2 r0 = srm[i];
                a0 = fmaf(r0.x, ex2(fmaf(vf, t.x, t.y) - r0.y), a0);
            }
            float cac = a0 + a1;
            if (!last6) {
                float c = first ? 1.f : sc[j];
                sc[j] = (cac == 0.f) ? 0.f : (c / fmaxf(c * cac, EPSV));
            } else {
                float arr = sc[j] * cac;       // approx_rank (sorted col)
                reg6[0][sidx[j]] = 1.f / (1.f + ex2(((float)(Nn - TOPK) - arr) * L2E));
            }
        }
        __syncthreads();
    }

    // ---------------- finals
    if (!isdiv) {
        // row#5 for rows 0..9 only, fused with approx_rel (thread-per-row)
        if (tid < TOPK) {
            int r = tid;
            int lh = slh[r];
            int lo = lh & 0xffff, hi = lh >> 16;
            float v = (float)(Nn - 1 - 2 * r);
            float mxx = smxx[r], inv = sinv[r];
            float racc = 0.f, ra = 0.f;
            for (int j = lo; j < hi; j++) {
                float2 t = sTB[j];
                float ce = sc[j] * ex2(fmaf(v, t.x, t.y) - mxx);
                racc += ce;
                ra = fmaf(ce, reg6[0][j], ra);
            }
            float rowsum = inv * racc;
            float rold = sr[r];
            float rn = (rowsum == 0.f) ? 0.f : (rold / fmaxf(rold * rowsum, EPSV));
            sarel[r] = rn * inv * ra;
        }
        if (w == 2) warp_top10_vals(reg6[1], lane, st10b);   // top-10 of relevance
        __syncthreads();
        if (tid == 0) {
            float da = 0.f, dm = 0.f, db = 0.f;
            for (int t = 0; t < TOPK; t++) {
                float disc = log2f((float)(t + 2));
                da += (exp2f(sarel[t]) - 1.f) / disc;
                dm += (exp2f(reg6[0][Nn - 1 - t]) - 1.f) / disc;  // rel at top-10 scores
                db += (exp2f(st10b[t]) - 1.f) / disc;
            }
            out[u]      = da / db;
            out[Uu + u] = dm / db;
        }
    } else {
        // top-10 mask: sorted positions 502..511
        if (tid < TOPK) ((int*)reg6[1])[sidx[Nn - 1 - tid]] = 1;
        __syncthreads();
        // item phase: warp per 64 items, lane owns feats {2l, 2l+1}
        float gx = 0.f, gy = 0.f, hx = 0.f, hy = 0.f;
        float s1 = 0.f, s2 = 0.f, q = 0.f, qh = 0.f;
        for (int ii = 0; ii < 64; ii++) {
            int j = (w << 6) + ii;
            const float2 xy = *(const float2*)(batch + ((size_t)(u * Nn + j)) * Ff + 2 * lane);
            float nr = xy.x * xy.x + xy.y * xy.y;
            nr = warp_sum(nr);
            float nrm = sqrtf(nr);
            float inv = 1.f / fmaxf(nrm, 1e-8f);
            float nn = nr * inv * inv;
            float a = reg6[0][j];
            gx += a * xy.x * inv; gy += a * xy.y * inv;
            int m = ((int*)reg6[1])[j];
            if (m) { hx += xy.x * inv; hy += xy.y * inv; }
            if (lane == 0) {
                s1 += a; s2 += a * a; q += a * a * nn;
                if (m) qh += nn;
            }
        }
        sbufA[(w << 6) + 2 * lane] = gx; sbufA[(w << 6) + 2 * lane + 1] = gy;
        sbufB[(w << 6) + 2 * lane] = hx; sbufB[(w << 6) + 2 * lane + 1] = hy;
        if (lane == 0) {
            sscal[w][0] = s1; sscal[w][1] = s2; sscal[w][2] = q; sscal[w][3] = qh;
        }
        __syncthreads();
        if (tid < FUF) {
            float gf = 0.f, hf = 0.f;
#pragma unroll
            for (int qq = 0; qq < 8; qq++) { gf += sbufA[(qq << 6) + tid]; hf += sbufB[(qq << 6) + tid]; }
            sfin[tid] = gf * gf;
            sfin[FUF + tid] = hf * hf;
        }
        __syncthreads();
        if (tid == 0) {
            float G2 = 0.f, H2 = 0.f;
            for (int f = 0; f < FUF; f++) { G2 += sfin[f]; H2 += sfin[FUF + f]; }
            float S1 = 0.f, S2v = 0.f, Q = 0.f, Qh = 0.f;
            for (int qq = 0; qq < 8; qq++) {
                S1 += sscal[qq][0]; S2v += sscal[qq][1];
                Q  += sscal[qq][2]; Qh  += sscal[qq][3];
            }
            float denomA = S1 * S1 - S2v;
            out[2 * Uu + u] = 1.f - (G2 - Q) / denomA;
            out[3 * Uu + u] = (45.f - 0.5f * (H2 - Qh)) / 45.f;
        }
    }
}

// ---------------------------------------------------------------------------
extern "C" void kernel_launch(void* const* d_in, const int* in_sizes, int n_in,
                              void* d_out, int out_size) {
    const float* batch  = (const float*)d_in[0];
    const float* s_div  = (const float*)d_in[1];
    const float* s_ndcg = (const float*)d_in[2];
    const float* rel    = (const float*)d_in[3];
    float* out = (float*)d_out;

    mega_kernel<<<256, 256>>>(batch, s_div, s_ndcg, rel, out);
}

// round 7
// speedup vs baseline: 4.0254x; 1.0867x over previous
#include <cuda_runtime.h>
#include <math.h>
#include <math_constants.h>

#define Uu    128
#define Nn    512
#define Ff    80
#define FUF   64
#define TOPK  10
#define NCH   16
#define EPSV  1e-10f
#define C10L2E 14.4269504088896340736f   // 10 * log2(e)
#define L2E    1.44269504088896340736f
#define THRX   80.0f                     // cutoff in ex2-arg units

__device__ __forceinline__ float ex2(float x) {
    float r;
    asm("ex2.approx.ftz.f32 %0, %1;" : "=f"(r) : "f"(x));
    return r;
}
__device__ __forceinline__ float warp_sum(float v) {
#pragma unroll
    for (int o = 16; o > 0; o >>= 1) v += __shfl_xor_sync(0xffffffffu, v, o);
    return v;
}

// warp-collective repeated argmax (value desc, index asc) over vals[0..511]
__device__ __forceinline__ void warp_top10_vals(const float* vals, int lane, float* outv) {
    float mv[16];
#pragma unroll
    for (int k = 0; k < 16; k++) mv[k] = vals[(k << 5) + lane];
    for (int t = 0; t < TOPK; t++) {
        float bv = -CUDART_INF_F; int bi = Nn;
#pragma unroll
        for (int k = 0; k < 16; k++) {
            int j = (k << 5) + lane;
            if (mv[k] > bv || (mv[k] == bv && j < bi)) { bv = mv[k]; bi = j; }
        }
#pragma unroll
        for (int o = 16; o > 0; o >>= 1) {
            float ov = __shfl_xor_sync(0xffffffffu, bv, o);
            int   oi = __shfl_xor_sync(0xffffffffu, bi, o);
            if (ov > bv || (ov == bv && oi < bi)) { bv = ov; bi = oi; }
        }
        outv[t] = bv;
        if ((bi & 31) == lane) mv[bi >> 5] = -CUDART_INF_F;
    }
}

__global__ void __launch_bounds__(512, 2) mega_kernel(
    const float* __restrict__ batch, const float* __restrict__ s_div,
    const float* __restrict__ s_ndcg, const float* __restrict__ rel_g,
    float* __restrict__ out)
{
    __shared__ float  sbufA[Nn], sbufB[Nn], sbufC[Nn];
    __shared__ float2 sTB[Nn];                 // (s*C, -A*C) per sorted column
    __shared__ float2 srm[Nn];                 // (rho, mxx) per row
    __shared__ int    sidx[Nn], slh[Nn];
    __shared__ float  smxx[Nn], sinv[Nn], sr[Nn], sc[Nn];
    __shared__ float  reg6[2][Nn];             // ndcg: rel_sorted / rel_raw ; div: rank / mask
    __shared__ int    scl[NCH], sch[NCH];
    __shared__ float  sarel[TOPK], st10b[TOPK];
    __shared__ float  sgp[16][FUF], shp[16][FUF];
    __shared__ float  sscal[16][4];
    __shared__ float  sfin[2 * FUF];

    int bid = blockIdx.x;
    int u = bid >> 1;
    bool isdiv = (bid & 1) != 0;
    int tid = threadIdx.x, w = tid >> 5, lane = tid & 31;

    // ---------------- setup (1 element per thread)
    const float* sp = isdiv ? (s_div + (size_t)u * Nn) : (s_ndcg + (size_t)u * Nn);
    float* sv = sbufA;
    sv[tid] = sp[tid];
    sidx[tid] = tid;
    sr[tid] = 1.0f;
    if (!isdiv) reg6[1][tid] = rel_g[(size_t)u * Nn + tid];
    else        ((int*)reg6[1])[tid] = 0;
    if (tid < NCH) { scl[tid] = Nn; sch[tid] = -1; }
    __syncthreads();

    // ---------------- bitonic sort ascending (value, tie: idx asc)
    for (int kk = 2; kk <= Nn; kk <<= 1) {
        for (int jj = kk >> 1; jj > 0; jj >>= 1) {
            int ixj = tid ^ jj;
            if (ixj > tid) {
                float va = sv[tid], vb = sv[ixj];
                int   ia = sidx[tid], ib = sidx[ixj];
                bool up = ((tid & kk) == 0);
                bool agtb = (va > vb) || (va == vb && ia > ib);
                if (agtb == up) { sv[tid] = vb; sv[ixj] = va; sidx[tid] = ib; sidx[ixj] = ia; }
            }
            __syncthreads();
        }
    }

    // ---------------- inclusive prefix scan (Hillis-Steele), then build TB
    {
        float* a  = sbufB;
        float* b2 = sbufC;
        a[tid] = sv[tid];
        __syncthreads();
        for (int d = 1; d < Nn; d <<= 1) {
            b2[tid] = a[tid] + ((tid >= d) ? a[tid - d] : 0.f);
            __syncthreads();
            float* tmp = a; a = b2; b2 = tmp;
        }
        float tot = a[Nn - 1];
        float ssj = sv[tid];
        float pre = a[tid] - ssj;
        float A = (float)(2 * tid - Nn) * ssj + tot - 2.f * pre;
        sTB[tid] = make_float2(ssj * C10L2E, -A * C10L2E);
        if (!isdiv) reg6[0][tid] = reg6[1][sidx[tid]];   // rel in sorted order
    }
    __syncthreads();

    // ---------------- per-row band: analytic peak j* = N-1-r, two binary searches
    {
        int r = tid;
        float v = (float)(Nn - 1 - 2 * r);
        int jstar = Nn - 1 - r;
        float2 tp = sTB[jstar];
        float mxx = fmaf(v, tp.x, tp.y);       // exact row max (x unimodal, peak at jstar)
        float thr = mxx - THRX;
        int a0 = 0, b0 = jstar;                // x nondecreasing on [0, jstar]
        while (a0 < b0) {
            int m = (a0 + b0) >> 1;
            float2 t = sTB[m];
            if (fmaf(v, t.x, t.y) >= thr) b0 = m; else a0 = m + 1;
        }
        int lo = a0;
        a0 = jstar; b0 = Nn - 1;               // x nonincreasing on [jstar, N-1]
        while (a0 < b0) {
            int m = (a0 + b0 + 1) >> 1;
            float2 t = sTB[m];
            if (fmaf(v, t.x, t.y) >= thr) a0 = m; else b0 = m - 1;
        }
        int hi = a0 + 1;
        slh[r] = lo | (hi << 16);
        smxx[r] = mxx;
        for (int ch = (lo >> 5); ch < ((hi + 31) >> 5); ch++) {
            atomicMin(&scl[ch], r);
            atomicMax(&sch[ch], r);
        }
    }
    __syncthreads();

    // cache per-thread row constants
    int   my_lh  = slh[tid];
    int   my_lo  = my_lh & 0xffff, my_hi = my_lh >> 16;
    float my_v   = (float)(Nn - 1 - 2 * tid);
    float my_mxx = smxx[tid];
    float2 my_tb = sTB[tid];
    int   my_ch  = tid >> 5;                    // warp-uniform chunk for pass B
    int   my_i0  = scl[my_ch], my_i1 = sch[my_ch];

    // ---------------- sweeps
    // sweep 0: col#1 (r=1).  sweeps 1..4: row#k + col#(k+1).
    // sweep 5 (div only): weighted row#5 + approx_rank.  ndcg row#5 in tail.
    int nsweep = isdiv ? 6 : 5;
    for (int sweep = 0; sweep < nsweep; sweep++) {
        bool first = (sweep == 0);
        bool last6 = (sweep == 5);
        // ---- pass A: thread-per-row, 4 accumulators
        {
            float a0 = 0.f, a1 = 0.f, a2 = 0.f, a3 = 0.f;
            int j = my_lo;
            if (first) {
                for (; j + 4 <= my_hi; j += 4) {
                    float2 t0 = sTB[j], t1 = sTB[j+1], t2v = sTB[j+2], t3 = sTB[j+3];
                    a0 += ex2(fmaf(my_v, t0.x,  t0.y)  - my_mxx);
                    a1 += ex2(fmaf(my_v, t1.x,  t1.y)  - my_mxx);
                    a2 += ex2(fmaf(my_v, t2v.x, t2v.y) - my_mxx);
                    a3 += ex2(fmaf(my_v, t3.x,  t3.y)  - my_mxx);
                }
                for (; j < my_hi; j++) {
                    float2 t0 = sTB[j];
                    a0 += ex2(fmaf(my_v, t0.x, t0.y) - my_mxx);
                }
            } else {
                for (; j + 4 <= my_hi; j += 4) {
                    float2 t0 = sTB[j], t1 = sTB[j+1], t2v = sTB[j+2], t3 = sTB[j+3];
                    float c0 = sc[j], c1 = sc[j+1], c2 = sc[j+2], c3 = sc[j+3];
                    a0 = fmaf(c0, ex2(fmaf(my_v, t0.x,  t0.y)  - my_mxx), a0);
                    a1 = fmaf(c1, ex2(fmaf(my_v, t1.x,  t1.y)  - my_mxx), a1);
                    a2 = fmaf(c2, ex2(fmaf(my_v, t2v.x, t2v.y) - my_mxx), a2);
                    a3 = fmaf(c3, ex2(fmaf(my_v, t3.x,  t3.y)  - my_mxx), a3);
                }
                for (; j < my_hi; j++) {
                    float2 t0 = sTB[j];
                    a0 = fmaf(sc[j], ex2(fmaf(my_v, t0.x, t0.y) - my_mxx), a0);
                }
            }
            float racc = (a0 + a1) + (a2 + a3);
            float rho;
            if (first) {
                float inv = 1.f / racc;        // racc >= 1 (exp at jstar == 1)
                sinv[tid] = inv;
                rho = inv;
            } else {
                float inv = sinv[tid];
                float rowsum = inv * racc;
                float rold = sr[tid];
                float rn = (rowsum == 0.f) ? 0.f : (rold / fmaxf(rold * rowsum, EPSV));
                if (!last6) sr[tid] = rn;
                rho = rn * inv;
                if (last6) rho *= (float)(Nn - tid);   // w_i = N - i
            }
            srm[tid] = make_float2(rho, my_mxx);
        }
        __syncthreads();
        // ---- pass B: thread-per-column; warp == one chunk, srm reads broadcast
        {
            float a0 = 0.f, a1 = 0.f, a2 = 0.f, a3 = 0.f;
            float vf = (float)(Nn - 1 - 2 * my_i0);
            int i = my_i0;
            for (; i + 4 <= my_i1 + 1; i += 4) {
                float2 r0 = srm[i], r1 = srm[i+1], r2 = srm[i+2], r3 = srm[i+3];
                a0 = fmaf(r0.x, ex2(fmaf(vf,       my_tb.x, my_tb.y) - r0.y), a0);
                a1 = fmaf(r1.x, ex2(fmaf(vf - 2.f, my_tb.x, my_tb.y) - r1.y), a1);
                a2 = fmaf(r2.x, ex2(fmaf(vf - 4.f, my_tb.x, my_tb.y) - r2.y), a2);
                a3 = fmaf(r3.x, ex2(fmaf(vf - 6.f, my_tb.x, my_tb.y) - r3.y), a3);
                vf -= 8.f;
            }
            for (; i <= my_i1; i++) {
                float2 r0 = srm[i];
                a0 = fmaf(r0.x, ex2(fmaf(vf, my_tb.x, my_tb.y) - r0.y), a0);
                vf -= 2.f;
            }
            float cac = (a0 + a1) + (a2 + a3);
            if (!last6) {
                float c = first ? 1.f : sc[tid];
                sc[tid] = (cac == 0.f) ? 0.f : (c / fmaxf(c * cac, EPSV));
            } else {
                float arr = sc[tid] * cac;     // approx_rank (sorted col)
                reg6[0][sidx[tid]] = 1.f / (1.f + ex2(((float)(Nn - TOPK) - arr) * L2E));
            }
        }
        __syncthreads();
    }

    // ---------------- finals
    if (!isdiv) {
        // row#5 for rows 0..9 only, fused with approx_rel (thread-per-row)
        if (tid < TOPK) {
            float racc = 0.f, ra = 0.f;
            for (int j = my_lo; j < my_hi; j++) {
                float2 t = sTB[j];
                float ce = sc[j] * ex2(fmaf(my_v, t.x, t.y) - my_mxx);
                racc += ce;
                ra = fmaf(ce, reg6[0][j], ra);
            }
            float rowsum = sinv[tid] * racc;
            float rold = sr[tid];
            float rn = (rowsum == 0.f) ? 0.f : (rold / fmaxf(rold * rowsum, EPSV));
            sarel[tid] = rn * sinv[tid] * ra;
        }
        if (w == 2) warp_top10_vals(reg6[1], lane, st10b);   // top-10 of relevance
        __syncthreads();
        if (tid == 0) {
            float da = 0.f, dm = 0.f, db = 0.f;
            for (int t = 0; t < TOPK; t++) {
                float disc = log2f((float)(t + 2));
                da += (exp2f(sarel[t]) - 1.f) / disc;
                dm += (exp2f(reg6[0][Nn - 1 - t]) - 1.f) / disc;  // rel at top-10 scores
                db += (exp2f(st10b[t]) - 1.f) / disc;
            }
            out[u]      = da / db;
            out[Uu + u] = dm / db;
        }
    } else {
        // top-10 mask: sorted positions 502..511
        if (tid < TOPK) ((int*)reg6[1])[sidx[Nn - 1 - tid]] = 1;
        __syncthreads();
        // item phase: warp per 32 items, lane owns feats {2l, 2l+1}
        float gx = 0.f, gy = 0.f, hx = 0.f, hy = 0.f;
        float s1 = 0.f, s2 = 0.f, q = 0.f, qh = 0.f;
        for (int ii = 0; ii < 32; ii++) {
            int j = (w << 5) + ii;
            const float2 xy = *(const float2*)(batch + ((size_t)(u * Nn + j)) * Ff + 2 * lane);
            float nr = xy.x * xy.x + xy.y * xy.y;
            nr = warp_sum(nr);
            float nrm = sqrtf(nr);
            float inv = 1.f / fmaxf(nrm, 1e-8f);
            float nn = nr * inv * inv;
            float a = reg6[0][j];
            gx += a * xy.x * inv; gy += a * xy.y * inv;
            int m = ((int*)reg6[1])[j];
            if (m) { hx += xy.x * inv; hy += xy.y * inv; }
            if (lane == 0) {
                s1 += a; s2 += a * a; q += a * a * nn;
                if (m) qh += nn;
            }
        }
        sgp[w][2 * lane] = gx; sgp[w][2 * lane + 1] = gy;
        shp[w][2 * lane] = hx; shp[w][2 * lane + 1] = hy;
        if (lane == 0) {
            sscal[w][0] = s1; sscal[w][1] = s2; sscal[w][2] = q; sscal[w][3] = qh;
        }
        __syncthreads();
        if (tid < FUF) {
            float gf = 0.f, hf = 0.f;
#pragma unroll
            for (int qq = 0; qq < 16; qq++) { gf += sgp[qq][tid]; hf += shp[qq][tid]; }
            sfin[tid] = gf * gf;
            sfin[FUF + tid] = hf * hf;
        }
        __syncthreads();
        if (tid == 0) {
            float G2 = 0.f, H2 = 0.f;
            for (int f = 0; f < FUF; f++) { G2 += sfin[f]; H2 += sfin[FUF + f]; }
            float S1 = 0.f, S2v = 0.f, Q = 0.f, Qh = 0.f;
            for (int qq = 0; qq < 16; qq++) {
                S1 += sscal[qq][0]; S2v += sscal[qq][1];
                Q  += sscal[qq][2]; Qh  += sscal[qq][3];
            }
            float denomA = S1 * S1 - S2v;
            out[2 * Uu + u] = 1.f - (G2 - Q) / denomA;
            out[3 * Uu + u] = (45.f - 0.5f * (H2 - Qh)) / 45.f;
        }
    }
}

// ---------------------------------------------------------------------------
extern "C" void kernel_launch(void* const* d_in, const int* in_sizes, int n_in,
                              void* d_out, int out_size) {
    const float* batch  = (const float*)d_in[0];
    const float* s_div  = (const float*)d_in[1];
    const float* s_ndcg = (const float*)d_in[2];
    const float* rel    = (const float*)d_in[3];
    float* out = (float*)d_out;

    mega_kernel<<<256, 512>>>(batch, s_div, s_ndcg, rel, out);
}

// round 8
// speedup vs baseline: 4.2933x; 1.0666x over previous
#include <cuda_runtime.h>
#include <math.h>
#include <math_constants.h>

#define Uu    128
#define Nn    512
#define Ff    80
#define FUF   64
#define TOPK  10
#define CHW   8
#define NCH   (Nn / CHW)
#define EPSV  1e-10f
#define C10L2E 14.4269504088896340736f   // 10 * log2(e)
#define L2E    1.44269504088896340736f
#define THRX   55.0f                     // cutoff in ex2-arg units

__device__ __forceinline__ float ex2(float x) {
    float r;
    asm("ex2.approx.ftz.f32 %0, %1;" : "=f"(r) : "f"(x));
    return r;
}
__device__ __forceinline__ float warp_sum(float v) {
#pragma unroll
    for (int o = 16; o > 0; o >>= 1) v += __shfl_xor_sync(0xffffffffu, v, o);
    return v;
}

// warp-collective repeated argmax (value desc, index asc) over vals[0..511]
__device__ __forceinline__ void warp_top10_vals(const float* vals, int lane, float* outv) {
    float mv[16];
#pragma unroll
    for (int k = 0; k < 16; k++) mv[k] = vals[(k << 5) + lane];
    for (int t = 0; t < TOPK; t++) {
        float bv = -CUDART_INF_F; int bi = Nn;
#pragma unroll
        for (int k = 0; k < 16; k++) {
            int j = (k << 5) + lane;
            if (mv[k] > bv || (mv[k] == bv && j < bi)) { bv = mv[k]; bi = j; }
        }
#pragma unroll
        for (int o = 16; o > 0; o >>= 1) {
            float ov = __shfl_xor_sync(0xffffffffu, bv, o);
            int   oi = __shfl_xor_sync(0xffffffffu, bi, o);
            if (ov > bv || (ov == bv && oi < bi)) { bv = ov; bi = oi; }
        }
        outv[t] = bv;
        if ((bi & 31) == lane) mv[bi >> 5] = -CUDART_INF_F;
    }
}

__global__ void __launch_bounds__(512, 2) mega_kernel(
    const float* __restrict__ batch, const float* __restrict__ s_div,
    const float* __restrict__ s_ndcg, const float* __restrict__ rel_g,
    float* __restrict__ out)
{
    __shared__ unsigned long long skey[Nn];    // sortable keys (flipped-float | idx)
    __shared__ float  ssort[Nn];               // sorted scores
    __shared__ float2 sTB[Nn];                 // (s*C, -A*C) per sorted column
    __shared__ float2 srm[Nn];                 // (rho, mxx) per row
    __shared__ int    sidx[Nn];
    __shared__ float  sc[Nn];
    __shared__ float  reg6[2][Nn];             // ndcg: rel_sorted / rel_raw ; div: rank / mask
    __shared__ int    scl[NCH], sch[NCH];
    __shared__ float  swarp[16];
    __shared__ float  sarel[TOPK], st10b[TOPK];
    __shared__ float  sgp[16][FUF], shp[16][FUF];
    __shared__ float  sscal[16][4];
    __shared__ float  sfin[2 * FUF];

    int bid = blockIdx.x;
    int u = bid >> 1;
    bool isdiv = (bid & 1) != 0;
    int tid = threadIdx.x, w = tid >> 5, lane = tid & 31;

    // ---------------- setup
    const float* sp = isdiv ? (s_div + (size_t)u * Nn) : (s_ndcg + (size_t)u * Nn);
    float myscore = sp[tid];
    float myrel = 0.f;
    if (!isdiv) { myrel = rel_g[(size_t)u * Nn + tid]; reg6[1][tid] = myrel; }
    {
        unsigned int ub = __float_as_uint(myscore);
        ub ^= (ub & 0x80000000u) ? 0xFFFFFFFFu : 0x80000000u;
        skey[tid] = ((unsigned long long)ub << 32) | (unsigned)tid;
    }
    if (tid < NCH) { scl[tid] = Nn; sch[tid] = -1; }
    __syncthreads();

    // ---------------- rank sort (barrier-free O(N) count per thread)
    {
        unsigned long long mykey = skey[tid];
        int rank = 0;
        const ulonglong2* kp = (const ulonglong2*)skey;
#pragma unroll 8
        for (int k2 = 0; k2 < Nn / 2; k2++) {
            ulonglong2 q = kp[k2];
            rank += (q.x < mykey) + (q.y < mykey);
        }
        ssort[rank] = myscore;
        sidx[rank] = tid;
        if (!isdiv) reg6[0][rank] = myrel;                 // rel in sorted order
        else ((int*)reg6[1])[tid] = (rank >= Nn - TOPK) ? 1 : 0;   // top-10 mask
    }
    __syncthreads();

    // ---------------- prefix scan (warp shuffles), build TB
    {
        float x = ssort[tid];
        float inc = x;
#pragma unroll
        for (int o = 1; o < 32; o <<= 1) {
            float up = __shfl_up_sync(0xffffffffu, inc, o);
            if (lane >= o) inc += up;
        }
        if (lane == 31) swarp[w] = inc;
        __syncthreads();
        if (w == 0) {
            float t = (lane < 16) ? swarp[lane] : 0.f;
#pragma unroll
            for (int o = 1; o < 16; o <<= 1) {
                float up = __shfl_up_sync(0xffffffffu, t, o);
                if (lane >= o) t += up;
            }
            if (lane < 16) swarp[lane] = t;
        }
        __syncthreads();
        float offs = (w > 0) ? swarp[w - 1] : 0.f;
        float tot = swarp[15];
        float incl = inc + offs;
        float pre = incl - x;
        float A = (float)(2 * tid - Nn) * x + tot - 2.f * pre;
        sTB[tid] = make_float2(x * C10L2E, -A * C10L2E);
    }
    __syncthreads();

    // ---------------- per-row band: analytic peak j* = N-1-r, two binary searches
    float my_v = (float)(Nn - 1 - 2 * tid);
    float my_mxx;
    int my_lo, my_hi;
    {
        int jstar = Nn - 1 - tid;
        float2 tp = sTB[jstar];
        my_mxx = fmaf(my_v, tp.x, tp.y);       // exact row max (x unimodal, peak at jstar)
        float thr = my_mxx - THRX;
        int a0 = 0, b0 = jstar;                // x nondecreasing on [0, jstar]
        while (a0 < b0) {
            int m = (a0 + b0) >> 1;
            float2 t = sTB[m];
            if (fmaf(my_v, t.x, t.y) >= thr) b0 = m; else a0 = m + 1;
        }
        my_lo = a0;
        a0 = jstar; b0 = Nn - 1;               // x nonincreasing on [jstar, N-1]
        while (a0 < b0) {
            int m = (a0 + b0 + 1) >> 1;
            float2 t = sTB[m];
            if (fmaf(my_v, t.x, t.y) >= thr) a0 = m; else b0 = m - 1;
        }
        my_hi = a0 + 1;
        for (int ch = (my_lo >> 3); ch < ((my_hi + CHW - 1) >> 3); ch++) {
            atomicMin(&scl[ch], tid);
            atomicMax(&sch[ch], tid);
        }
    }
    __syncthreads();

    float2 my_tb = sTB[tid];
    int my_ch = tid >> 3;
    int my_i0 = scl[my_ch], my_i1 = sch[my_ch];
    float my_r = 1.0f, my_inv = 1.0f;

    // ---------------- sweeps
    // sweep 0: col#1 (r=1).  sweeps 1..4: row#k + col#(k+1).
    // sweep 5 (div only): weighted row#5 + approx_rank.  ndcg row#5 in tail.
    int nsweep = isdiv ? 6 : 5;
    for (int sweep = 0; sweep < nsweep; sweep++) {
        bool first = (sweep == 0);
        bool last6 = (sweep == 5);
        // ---- pass A: thread-per-row, 4 accumulators
        {
            float a0 = 0.f, a1 = 0.f, a2 = 0.f, a3 = 0.f;
            int j = my_lo;
            if (first) {
                for (; j + 4 <= my_hi; j += 4) {
                    float2 t0 = sTB[j], t1 = sTB[j+1], t2v = sTB[j+2], t3 = sTB[j+3];
                    a0 += ex2(fmaf(my_v, t0.x,  t0.y)  - my_mxx);
                    a1 += ex2(fmaf(my_v, t1.x,  t1.y)  - my_mxx);
                    a2 += ex2(fmaf(my_v, t2v.x, t2v.y) - my_mxx);
                    a3 += ex2(fmaf(my_v, t3.x,  t3.y)  - my_mxx);
                }
                for (; j < my_hi; j++) {
                    float2 t0 = sTB[j];
                    a0 += ex2(fmaf(my_v, t0.x, t0.y) - my_mxx);
                }
            } else {
                for (; j + 4 <= my_hi; j += 4) {
                    float2 t0 = sTB[j], t1 = sTB[j+1], t2v = sTB[j+2], t3 = sTB[j+3];
                    float c0 = sc[j], c1 = sc[j+1], c2 = sc[j+2], c3 = sc[j+3];
                    a0 = fmaf(c0, ex2(fmaf(my_v, t0.x,  t0.y)  - my_mxx), a0);
                    a1 = fmaf(c1, ex2(fmaf(my_v, t1.x,  t1.y)  - my_mxx), a1);
                    a2 = fmaf(c2, ex2(fmaf(my_v, t2v.x, t2v.y) - my_mxx), a2);
                    a3 = fmaf(c3, ex2(fmaf(my_v, t3.x,  t3.y)  - my_mxx), a3);
                }
                for (; j < my_hi; j++) {
                    float2 t0 = sTB[j];
                    a0 = fmaf(sc[j], ex2(fmaf(my_v, t0.x, t0.y) - my_mxx), a0);
                }
            }
            float racc = (a0 + a1) + (a2 + a3);
            float rho;
            if (first) {
                my_inv = 1.f / racc;           // racc >= 1 (exp at jstar == 1)
                rho = my_inv;
            } else {
                float rowsum = my_inv * racc;
                float rn = (rowsum == 0.f) ? 0.f : (my_r / fmaxf(my_r * rowsum, EPSV));
                if (!last6) my_r = rn;
                rho = rn * my_inv;
                if (last6) rho *= (float)(Nn - tid);   // w_i = N - i
            }
            srm[tid] = make_float2(rho, my_mxx);
        }
        __syncthreads();
        // ---- pass B: thread-per-column; trip count = own chunk's row range
        {
            float a0 = 0.f, a1 = 0.f, a2 = 0.f, a3 = 0.f;
            float vf = (float)(Nn - 1 - 2 * my_i0);
            int i = my_i0;
            for (; i + 4 <= my_i1 + 1; i += 4) {
                float2 r0 = srm[i], r1 = srm[i+1], r2 = srm[i+2], r3 = srm[i+3];
                a0 = fmaf(r0.x, ex2(fmaf(vf,       my_tb.x, my_tb.y) - r0.y), a0);
                a1 = fmaf(r1.x, ex2(fmaf(vf - 2.f, my_tb.x, my_tb.y) - r1.y), a1);
                a2 = fmaf(r2.x, ex2(fmaf(vf - 4.f, my_tb.x, my_tb.y) - r2.y), a2);
                a3 = fmaf(r3.x, ex2(fmaf(vf - 6.f, my_tb.x, my_tb.y) - r3.y), a3);
                vf -= 8.f;
            }
            for (; i <= my_i1; i++) {
                float2 r0 = srm[i];
                a0 = fmaf(r0.x, ex2(fmaf(vf, my_tb.x, my_tb.y) - r0.y), a0);
                vf -= 2.f;
            }
            float cac = (a0 + a1) + (a2 + a3);
            if (!last6) {
                float c = first ? 1.f : sc[tid];
                sc[tid] = (cac == 0.f) ? 0.f : (c / fmaxf(c * cac, EPSV));
            } else {
                float arr = sc[tid] * cac;     // approx_rank (sorted col)
                reg6[0][sidx[tid]] = 1.f / (1.f + ex2(((float)(Nn - TOPK) - arr) * L2E));
            }
        }
        __syncthreads();
    }

    // ---------------- finals
    if (!isdiv) {
        // row#5 for rows 0..9 only, fused with approx_rel (thread-per-row)
        if (tid < TOPK) {
            float racc = 0.f, ra = 0.f;
            for (int j = my_lo; j < my_hi; j++) {
                float2 t = sTB[j];
                float ce = sc[j] * ex2(fmaf(my_v, t.x, t.y) - my_mxx);
                racc += ce;
                ra = fmaf(ce, reg6[0][j], ra);
            }
            float rowsum = my_inv * racc;
            float rn = (rowsum == 0.f) ? 0.f : (my_r / fmaxf(my_r * rowsum, EPSV));
            sarel[tid] = rn * my_inv * ra;
        }
        if (w == 2) warp_top10_vals(reg6[1], lane, st10b);   // top-10 of relevance
        __syncthreads();
        if (tid == 0) {
            float da = 0.f, dm = 0.f, db = 0.f;
            for (int t = 0; t < TOPK; t++) {
                float disc = log2f((float)(t + 2));
                da += (exp2f(sarel[t]) - 1.f) / disc;
                dm += (exp2f(reg6[0][Nn - 1 - t]) - 1.f) / disc;  // rel at top-10 scores
                db += (exp2f(st10b[t]) - 1.f) / disc;
            }
            out[u]      = da / db;
            out[Uu + u] = dm / db;
        }
    } else {
        // item phase: warp per 32 items, lane owns feats {2l, 2l+1}
        float gx = 0.f, gy = 0.f, hx = 0.f, hy = 0.f;
        float s1 = 0.f, s2 = 0.f, q = 0.f, qh = 0.f;
        for (int ii = 0; ii < 32; ii++) {
            int j = (w << 5) + ii;
            const float2 xy = *(const float2*)(batch + ((size_t)(u * Nn + j)) * Ff + 2 * lane);
            float nr = xy.x * xy.x + xy.y * xy.y;
            nr = warp_sum(nr);
            float nrm = sqrtf(nr);
            float inv = 1.f / fmaxf(nrm, 1e-8f);
            float nn = nr * inv * inv;
            float a = reg6[0][j];
            gx += a * xy.x * inv; gy += a * xy.y * inv;
            int m = ((int*)reg6[1])[j];
            if (m) { hx += xy.x * inv; hy += xy.y * inv; }
            if (lane == 0) {
                s1 += a; s2 += a * a; q += a * a * nn;
                if (m) qh += nn;
            }
        }
        sgp[w][2 * lane] = gx; sgp[w][2 * lane + 1] = gy;
        shp[w][2 * lane] = hx; shp[w][2 * lane + 1] = hy;
        if (lane == 0) {
            sscal[w][0] = s1; sscal[w][1] = s2; sscal[w][2] = q; sscal[w][3] = qh;
        }
        __syncthreads();
        if (tid < FUF) {
            float gf = 0.f, hf = 0.f;
#pragma unroll
            for (int qq = 0; qq < 16; qq++) { gf += sgp[qq][tid]; hf += shp[qq][tid]; }
            sfin[tid] = gf * gf;
            sfin[FUF + tid] = hf * hf;
        }
        __syncthreads();
        if (tid == 0) {
            float G2 = 0.f, H2 = 0.f;
            for (int f = 0; f < FUF; f++) { G2 += sfin[f]; H2 += sfin[FUF + f]; }
            float S1 = 0.f, S2v = 0.f, Q = 0.f, Qh = 0.f;
            for (int qq = 0; qq < 16; qq++) {
                S1 += sscal[qq][0]; S2v += sscal[qq][1];
                Q  += sscal[qq][2]; Qh  += sscal[qq][3];
            }
            float denomA = S1 * S1 - S2v;
            out[2 * Uu + u] = 1.f - (G2 - Q) / denomA;
            out[3 * Uu + u] = (45.f - 0.5f * (H2 - Qh)) / 45.f;
        }
    }
}

// ---------------------------------------------------------------------------
extern "C" void kernel_launch(void* const* d_in, const int* in_sizes, int n_in,
                              void* d_out, int out_size) {
    const float* batch  = (const float*)d_in[0];
    const float* s_div  = (const float*)d_in[1];
    const float* s_ndcg = (const float*)d_in[2];
    const float* rel    = (const float*)d_in[3];
    float* out = (float*)d_out;

    mega_kernel<<<256, 512>>>(batch, s_div, s_ndcg, rel, out);
}